// round 14
// baseline (speedup 1.0000x reference)
#include <cuda_runtime.h>
#include <cuda.h>
#include <math.h>
#include <stdint.h>

// Fixed shape: H=1024, B=64, T=1024
#define BB 64
#define TS 1024
#define HS 1024
#define TCH 16                       // t per tile
#define NTILES 4096                  // 64 b * 64 t-chunks
#define GRIDN 152
#define NTHR 512
#define DEPTH 3
#define TILE_FLOATS (HS * TCH)       // 16384
#define TILE_BYTES (TILE_FLOATS * 4) // 64 KB
#define L2E 1.44269504088896340736f

// dynamic smem layout (floats)
#define F_DH  (DEPTH * TILE_FLOATS)  // 49152: dh slice (1024)
#define F_SA  (F_DH + 1024)          // stats partials, pitch 17: [16w][16t]
#define F_SB  (F_SA + 272)
#define F_SC  (F_SB + 272)
#define F_SD  (F_SC + 272)           // denom partials
#define F_FS  (F_SD + 272)           // scF[16]
#define F_FM  (F_FS + 16)            // MF[16]
#define F_FI  (F_FM + 16)            // inv[16]
#define F_END (F_FI + 16)
#define B_MBAR (F_END * 4)
#define SMEM_BYTES (B_MBAR + DEPTH * 8)   // ~205.3 KB

__device__ __forceinline__ uint32_t smem_u32(const void* p) {
    return (uint32_t)__cvta_generic_to_shared(p);
}
__device__ __forceinline__ void mbar_init(uint32_t a, uint32_t cnt) {
    asm volatile("mbarrier.init.shared.b64 [%0], %1;" :: "r"(a), "r"(cnt) : "memory");
}
#define MB_WAIT(addr, parity) do {                                              \
    uint32_t _m = (addr), _p = (parity), _d;                                    \
    asm volatile("{\n\t.reg .pred p;\n\t"                                       \
        "mbarrier.try_wait.parity.acquire.cta.shared::cta.b64 p, [%1], %2;\n\t" \
        "selp.b32 %0, 1, 0, p;\n\t}" : "=r"(_d) : "r"(_m), "r"(_p) : "memory"); \
    if (!_d) {                                                                  \
        asm volatile("{\n\t.reg .pred P1;\n\tW%=:\n\t"                          \
            "mbarrier.try_wait.parity.acquire.cta.shared::cta.b64 P1, [%0], %1, 0x989680;\n\t" \
            "@P1 bra.uni D%=;\n\tbra.uni W%=;\n\tD%=:\n\t}"                     \
            :: "r"(_m), "r"(_p) : "memory");                                    \
    }                                                                           \
} while (0)

// One 64KB tile (tile id m) into ring slot s: expect_tx + 4 x 3D TMA.
__device__ __forceinline__ void tma_issue(const CUtensorMap& tmap, uint32_t sb,
                                          uint32_t MB, int s, int m) {
    const int c = m & 63, b = m >> 6;
    const uint32_t mb = MB + (uint32_t)s * 8;
    asm volatile("mbarrier.arrive.expect_tx.shared.b64 _, [%0], %1;"
                 :: "r"(mb), "r"((uint32_t)TILE_BYTES) : "memory");
    const uint32_t dst = sb + (uint32_t)s * TILE_BYTES;
    #pragma unroll
    for (int k = 0; k < 4; ++k) {
        asm volatile(
            "cp.async.bulk.tensor.3d.shared::cta.global.tile.mbarrier::complete_tx::bytes "
            "[%0], [%1, {%2, %3, %4}], [%5];"
            :: "r"(dst + (uint32_t)k * 16384), "l"(&tmap),
               "r"(c * TCH), "r"(b), "r"(k * 256), "r"(mb) : "memory");
    }
}

// In-register 16x16 transpose-reduce over half-warp lanes (hw = lane & 15).
__device__ __forceinline__ void tr_reduce16(float* a, int hw) {
    #pragma unroll
    for (int s = 8; s >= 1; s >>= 1) {
        const bool up = (hw & s) != 0;
        #pragma unroll
        for (int i = 0; i < s; ++i) {
            const float give = up ? a[i] : a[i + s];
            const float keep = up ? a[i + s] : a[i];
            const float got  = __shfl_xor_sync(0xffffffffu, give, s);
            a[i] = keep + got;
        }
    }
}

__global__ void __launch_bounds__(1024)
zero_out(float* __restrict__ out) {
    out[blockIdx.x * 1024 + threadIdx.x] = 0.0f;
}

__global__ void __launch_bounds__(NTHR, 1)
attn_main(const __grid_constant__ CUtensorMap tmap,
          const float* __restrict__ dh, float* __restrict__ out) {
    extern __shared__ float smem[];
    const uint32_t sb = smem_u32(smem);
    const uint32_t MB = sb + B_MBAR;
    float* dhs   = smem + F_DH;
    float* sredA = smem + F_SA;      // [16 w][16 t] pitch 17
    float* sredB = smem + F_SB;
    float* sredC = smem + F_SC;
    float* sredD = smem + F_SD;
    float* finS  = smem + F_FS;
    float* finM  = smem + F_FM;
    float* finI  = smem + F_FI;

    const int tid = threadIdx.x;
    const int w = tid >> 5, l = tid & 31;
    const int t = l & 15, hr = l >> 4;
    const int R = w * 2 + hr;        // row residue mod 32; rows R + 32*i, i < 32

    const int start = (int)(((long long)blockIdx.x * NTILES) / GRIDN);
    const int end   = (int)(((long long)(blockIdx.x + 1) * NTILES) / GRIDN);
    const int ng    = end - start;

    if (tid == 0)
        for (int s = 0; s < DEPTH; ++s) mbar_init(MB + s * 8, 1);
    __syncthreads();

    if (tid == 0)
        for (int kk = 0; kk < DEPTH && kk < ng; ++kk)
            tma_issue(tmap, sb, MB, kk, start + kk);

    float vA[32], vB[32];
    int bcur = -1;

    // Pipeline: tile j lives in buf[j&1].
    //   A(k): exp(k-1) [uses finS/finM from B(k-1)],
    //         finalize(k-2) [uses finI from B(k-1)] -> atomics,
    //         load+stats(k) into buf[k&1].
    //   B(k): fold stats(k) -> finS/finM; fold denom(k-1) -> finI; TMA refill.
    for (int k = 0; k <= ng + 1; ++k) {
        float* bufP = ((k - 1) & 1) ? vB : vA;   // tile k-1
        float* bufQ = (k & 1) ? vB : vA;         // tile k-2, then tile k

        // ---- A: exp(k-1) + denominator partials ----
        if (k >= 1 && k <= ng) {
            const float scF = finS[t];
            const float MF  = finM[t];
            float ds = 0.f;
            #pragma unroll
            for (int i = 0; i < 32; ++i) {
                bufP[i] = exp2f(fmaf(bufP[i], scF, -MF));
                ds += bufP[i];
            }
            ds += __shfl_xor_sync(~0u, ds, 16);
            if (l < 16) sredD[w * 17 + l] = ds;
        }

        // ---- A: finalize tile k-2 (scale + reduce over t + atomic) ----
        if (k >= 2) {
            const int j = k - 2;
            const float inv = finI[t];
            #pragma unroll
            for (int i = 0; i < 32; ++i) bufQ[i] *= inv;
            tr_reduce16(bufQ, t);
            tr_reduce16(bufQ + 16, t);
            const int bj = (start + j) >> 6;
            atomicAdd(out + bj * HS + R + 32 * t,        bufQ[0]);
            atomicAdd(out + bj * HS + R + 32 * (16 + t), bufQ[16]);
        }

        // ---- A: load + stats of tile k ----
        if (k < ng) {
            const int b = (start + k) >> 6;
            if (b != bcur) {             // <= 2 times per CTA
                __syncthreads();
                if (tid < 256)
                    reinterpret_cast<float4*>(dhs)[tid] =
                        __ldg(reinterpret_cast<const float4*>(dh + b * HS) + tid);
                bcur = b;
                __syncthreads();
            }
            MB_WAIT(MB + (k % DEPTH) * 8, (k / DEPTH) & 1);

            // element (row, t) at tile[row*16 + t]; bank = 16*hr + t = lane id
            const float* tp = smem + (k % DEPTH) * TILE_FLOATS + R * 16 + t;
            const float* dp = dhs + R;
            float sp = 0.f, mx = -INFINITY, mn = INFINITY;
            #pragma unroll
            for (int i = 0; i < 32; ++i) {
                bufQ[i] = tp[i * 512];
                sp = fmaf(bufQ[i], dp[i * 32], sp);
                mx = fmaxf(mx, bufQ[i]);
                mn = fminf(mn, bufQ[i]);
            }
            sp += __shfl_xor_sync(~0u, sp, 16);
            mx = fmaxf(mx, __shfl_xor_sync(~0u, mx, 16));
            mn = fminf(mn, __shfl_xor_sync(~0u, mn, 16));
            if (l < 16) {
                sredA[w * 17 + l] = sp;
                sredB[w * 17 + l] = mx;
                sredC[w * 17 + l] = mn;
            }
        }
        __syncthreads();   // bar1: partials + denoms posted; slot consumed

        // ---- B: parallel folds + refill ----
        if (k < ng && w < 4) {           // stats fold: warp w -> t in [4w, 4w+4)
            const int tt = w * 4 + (l >> 3), e = l & 7;
            float sc = sredA[e * 17 + tt] + sredA[(e + 8) * 17 + tt];
            float X  = fmaxf(sredB[e * 17 + tt], sredB[(e + 8) * 17 + tt]);
            float N  = fminf(sredC[e * 17 + tt], sredC[(e + 8) * 17 + tt]);
            #pragma unroll
            for (int off = 1; off <= 4; off <<= 1) {
                sc += __shfl_xor_sync(~0u, sc, off);
                X = fmaxf(X, __shfl_xor_sync(~0u, X, off));
                N = fminf(N, __shfl_xor_sync(~0u, N, off));
            }
            if (e == 0) {
                const float M = (sc >= 0.f) ? X * sc : N * sc;  // exact max_h(v*s)
                finS[tt] = sc * L2E;
                finM[tt] = M * L2E;
            }
        }
        if (k >= 1 && k <= ng && w >= 4 && w < 8) {   // denom fold for tile k-1
            const int tt = (w - 4) * 4 + (l >> 3), e = l & 7;
            float d = sredD[e * 17 + tt] + sredD[(e + 8) * 17 + tt];
            #pragma unroll
            for (int off = 1; off <= 4; off <<= 1)
                d += __shfl_xor_sync(~0u, d, off);
            if (e == 0) finI[tt] = 1.0f / d;
        }
        if (tid == 256 && k + DEPTH < ng)    // warp 8: refill freed slot
            tma_issue(tmap, sb, MB, k % DEPTH, start + k + DEPTH);
        __syncthreads();   // bar2: fin published
    }
}

extern "C" void kernel_launch(void* const* d_in, const int* in_sizes, int n_in,
                              void* d_out, int out_size) {
    const float* dh  = (const float*)d_in[0];
    const float* enc = (const float*)d_in[1];
    if (n_in >= 2 && in_sizes[0] > in_sizes[1]) {
        enc = (const float*)d_in[0];
        dh  = (const float*)d_in[1];
    }
    float* out = (float*)d_out;

    typedef CUresult (*EncodeFn)(
        CUtensorMap*, CUtensorMapDataType, cuuint32_t, void*,
        const cuuint64_t*, const cuuint64_t*, const cuuint32_t*, const cuuint32_t*,
        CUtensorMapInterleave, CUtensorMapSwizzle, CUtensorMapL2promotion,
        CUtensorMapFloatOOBfill);
    void* fp = nullptr;
    cudaDriverEntryPointQueryResult qres;
#if CUDART_VERSION >= 12050
    cudaGetDriverEntryPointByVersion("cuTensorMapEncodeTiled", &fp, 12030,
                                     cudaEnableDefault, &qres);
#else
    cudaGetDriverEntryPoint("cuTensorMapEncodeTiled", &fp, cudaEnableDefault, &qres);
#endif
    CUtensorMap tmap;
    {
        EncodeFn fn = (EncodeFn)fp;
        cuuint64_t dims[3]    = {TS, BB, HS};
        cuuint64_t strides[2] = {TS * 4ull, (cuuint64_t)BB * TS * 4ull};
        cuuint32_t box[3]     = {TCH, 1, 256};
        cuuint32_t es[3]      = {1, 1, 1};
        fn(&tmap, CU_TENSOR_MAP_DATA_TYPE_FLOAT32, 3, (void*)enc,
           dims, strides, box, es,
           CU_TENSOR_MAP_INTERLEAVE_NONE, CU_TENSOR_MAP_SWIZZLE_NONE,
           CU_TENSOR_MAP_L2_PROMOTION_L2_128B, CU_TENSOR_MAP_FLOAT_OOB_FILL_NONE);
    }

    cudaFuncSetAttribute(attn_main,
                         cudaFuncAttributeMaxDynamicSharedMemorySize, SMEM_BYTES);
    zero_out<<<64, 1024>>>(out);
    attn_main<<<GRIDN, NTHR, SMEM_BYTES>>>(tmap, dh, out);
}

// round 17
// speedup vs baseline: 1.0867x; 1.0867x over previous
#include <cuda_runtime.h>
#include <cuda.h>
#include <math.h>
#include <stdint.h>

// Fixed shape: H=1024, B=64, T=1024
#define BB 64
#define TS 1024
#define HS 1024
#define TCH 16                        // t per tile
#define NTILES 4096                   // 64 b * 64 t-chunks
#define GRIDN 152
#define NCW 16                        // consumer warps
#define NTHR ((NCW + 1) * 32)         // 544: +1 producer warp
#define DEPTH 3
#define TILE_BYTES 65536
#define L2E 1.44269504088896340736f

// smem layout (bytes)
#define B_DH   (DEPTH * TILE_BYTES)   // dhs[2][1024] floats = 8192 B
#define B_SRED (B_DH + 8192)          // S/X/N/D: 4 x [16][4] floats = 1024 B
#define B_MBAR (B_SRED + 1024)        // full s*16, empty s*16+8
#define SMEM_BYTES (B_MBAR + DEPTH * 16)   // ~205.9 KB

__device__ __forceinline__ uint32_t smem_u32(const void* p) {
    return (uint32_t)__cvta_generic_to_shared(p);
}
__device__ __forceinline__ void mbar_init(uint32_t a, uint32_t cnt) {
    asm volatile("mbarrier.init.shared.b64 [%0], %1;" :: "r"(a), "r"(cnt) : "memory");
}
__device__ __forceinline__ void mbar_arrive(uint32_t a) {
    asm volatile("mbarrier.arrive.shared.b64 _, [%0];" :: "r"(a) : "memory");
}
#define MB_WAIT(addr, parity) do {                                              \
    uint32_t _m = (addr), _p = (parity), _d;                                    \
    asm volatile("{\n\t.reg .pred p;\n\t"                                       \
        "mbarrier.try_wait.parity.acquire.cta.shared::cta.b64 p, [%1], %2;\n\t" \
        "selp.b32 %0, 1, 0, p;\n\t}" : "=r"(_d) : "r"(_m), "r"(_p) : "memory"); \
    if (!_d) {                                                                  \
        asm volatile("{\n\t.reg .pred P1;\n\tW%=:\n\t"                          \
            "mbarrier.try_wait.parity.acquire.cta.shared::cta.b64 P1, [%0], %1, 0x989680;\n\t" \
            "@P1 bra.uni D%=;\n\tbra.uni W%=;\n\tD%=:\n\t}"                     \
            :: "r"(_m), "r"(_p) : "memory");                                    \
    }                                                                           \
} while (0)

// One 64KB tile (tile id m) into ring slot s: expect_tx + 4 x 3D TMA (SW64).
__device__ __forceinline__ void tma_issue(const CUtensorMap& tmap, uint32_t sb,
                                          uint32_t MB, int s, int m) {
    const int c = m & 63, b = m >> 6;
    const uint32_t mb = MB + (uint32_t)s * 16;
    asm volatile("mbarrier.arrive.expect_tx.shared.b64 _, [%0], %1;"
                 :: "r"(mb), "r"((uint32_t)TILE_BYTES) : "memory");
    const uint32_t dst = sb + (uint32_t)s * TILE_BYTES;
    #pragma unroll
    for (int k = 0; k < 4; ++k) {
        asm volatile(
            "cp.async.bulk.tensor.3d.shared::cta.global.tile.mbarrier::complete_tx::bytes "
            "[%0], [%1, {%2, %3, %4}], [%5];"
            :: "r"(dst + (uint32_t)k * 16384), "l"(&tmap),
               "r"(c * TCH), "r"(b), "r"(k * 256), "r"(mb) : "memory");
    }
}

__global__ void __launch_bounds__(1024)
zero_out(float* __restrict__ out) {
    out[blockIdx.x * 1024 + threadIdx.x] = 0.0f;
}

__global__ void __launch_bounds__(NTHR, 1)
attn_main(const __grid_constant__ CUtensorMap tmap,
          const float* __restrict__ dh, float* __restrict__ out) {
    extern __shared__ float smem[];
    const uint32_t sb = smem_u32(smem);
    const uint32_t MB = sb + B_MBAR;
    float* dhs   = (float*)((char*)smem + B_DH);
    float* sredS = (float*)((char*)smem + B_SRED);   // [q*4+rh][4]
    float* sredX = sredS + 64;
    float* sredN = sredX + 64;
    float* sredD = sredN + 64;

    const int tid = threadIdx.x;
    const int w = tid >> 5, l = tid & 31;

    const int start = (int)(((long long)blockIdx.x * NTILES) / GRIDN);
    const int end   = (int)(((long long)(blockIdx.x + 1) * NTILES) / GRIDN);
    const int ng    = end - start;

    if (tid == 0) {
        for (int s = 0; s < DEPTH; ++s) {
            mbar_init(MB + s * 16, 1);        // full: tx-based
            mbar_init(MB + s * 16 + 8, NCW);  // empty: one arrive per consumer warp
        }
    }
    __syncthreads();   // the only CTA-wide sync

    if (w == NCW) {
        // ---------------- producer warp (free-running) ----------------
        for (int k = 0; k < ng; ++k) {
            const int m = start + k;
            const int s = k % DEPTH;
            if (k >= DEPTH)
                MB_WAIT(MB + s * 16 + 8, ((k - DEPTH) / DEPTH) & 1);
            if (k == 0 || (m & 63) == 0) {
                const int b = m >> 6;
                float* dst = dhs + (b & 1) * HS;
                const float* src = dh + b * HS + l;
                #pragma unroll
                for (int j = 0; j < 32; ++j)
                    dst[l + 32 * j] = __ldg(src + 32 * j);
            }
            __syncwarp();
            if (l == 0)
                tma_issue(tmap, sb, MB, s, m);   // arrive has release semantics
        }
    } else {
        // -------- consumer warp: t-quad q (4 t's), row-quarter rh (256 h) --------
        const int q = w & 3, rh = w >> 2;
        const int barid = q + 1;                 // named barrier per quad-group
        // SW64 swizzle of logical (row=l)*64 + q*16, plus chunk base rh*16KB
        const uint32_t x0 = ((uint32_t)l << 6) | ((uint32_t)q << 4);
        const uint32_t xs = (x0 ^ ((x0 >> 3) & 0x30)) + (uint32_t)rh * 16384;
        const int rbase = rh * 256 + l;          // rows rbase + 32*i, i < 8

        float acc[8];
        #pragma unroll
        for (int i = 0; i < 8; ++i) acc[i] = 0.f;

        int bcur = -1;
        for (int k = 0; k < ng; ++k) {
            const int m = start + k;
            const int b = m >> 6;
            const int s = k % DEPTH;
            if (b != bcur) {
                if (bcur >= 0) {
                    #pragma unroll
                    for (int i = 0; i < 8; ++i) {
                        atomicAdd(out + bcur * HS + rbase + 32 * i, acc[i]);
                        acc[i] = 0.f;
                    }
                }
                bcur = b;
            }
            MB_WAIT(MB + s * 16, (k / DEPTH) & 1);

            // tile slice -> registers: 8 conflict-free LDS.128 + fused dot/max/min
            const char* tb = (const char*)smem + (size_t)s * TILE_BYTES + xs;
            const float* dp = dhs + (b & 1) * HS + rbase;
            float4 v[8];
            float sp0=0.f, sp1=0.f, sp2=0.f, sp3=0.f;
            float x0m=-INFINITY, x1m=-INFINITY, x2m=-INFINITY, x3m=-INFINITY;
            float n0m= INFINITY, n1m= INFINITY, n2m= INFINITY, n3m= INFINITY;
            #pragma unroll
            for (int i = 0; i < 8; ++i) {
                v[i] = *(const float4*)(tb + i * 2048);
                const float dv = dp[32 * i];
                sp0 = fmaf(v[i].x, dv, sp0);
                sp1 = fmaf(v[i].y, dv, sp1);
                sp2 = fmaf(v[i].z, dv, sp2);
                sp3 = fmaf(v[i].w, dv, sp3);
                x0m = fmaxf(x0m, v[i].x); n0m = fminf(n0m, v[i].x);
                x1m = fmaxf(x1m, v[i].y); n1m = fminf(n1m, v[i].y);
                x2m = fmaxf(x2m, v[i].z); n2m = fminf(n2m, v[i].z);
                x3m = fmaxf(x3m, v[i].w); n3m = fminf(n3m, v[i].w);
            }
            #pragma unroll
            for (int off = 16; off; off >>= 1) {
                sp0 += __shfl_xor_sync(~0u, sp0, off);
                sp1 += __shfl_xor_sync(~0u, sp1, off);
                sp2 += __shfl_xor_sync(~0u, sp2, off);
                sp3 += __shfl_xor_sync(~0u, sp3, off);
                x0m = fmaxf(x0m, __shfl_xor_sync(~0u, x0m, off));
                x1m = fmaxf(x1m, __shfl_xor_sync(~0u, x1m, off));
                x2m = fmaxf(x2m, __shfl_xor_sync(~0u, x2m, off));
                x3m = fmaxf(x3m, __shfl_xor_sync(~0u, x3m, off));
                n0m = fminf(n0m, __shfl_xor_sync(~0u, n0m, off));
                n1m = fminf(n1m, __shfl_xor_sync(~0u, n1m, off));
                n2m = fminf(n2m, __shfl_xor_sync(~0u, n2m, off));
                n3m = fminf(n3m, __shfl_xor_sync(~0u, n3m, off));
            }
            // all lanes' LDS proven complete (shfl consumed them) -> free the slot
            if (l == 0) {
                mbar_arrive(MB + s * 16 + 8);
                float* pS = sredS + (q * 4 + rh) * 4;
                pS[0]=sp0; pS[1]=sp1; pS[2]=sp2; pS[3]=sp3;
                float* pX = sredX + (q * 4 + rh) * 4;
                pX[0]=x0m; pX[1]=x1m; pX[2]=x2m; pX[3]=x3m;
                float* pN = sredN + (q * 4 + rh) * 4;
                pN[0]=n0m; pN[1]=n1m; pN[2]=n2m; pN[3]=n3m;
            }
            asm volatile("bar.sync %0, 128;" :: "r"(barid) : "memory");

            // fold 4 row-quarters -> exact full-H stats for my 4 t's
            float scF[4], MF[4];
            #pragma unroll
            for (int j = 0; j < 4; ++j) {
                const int g0 = q * 16 + j;
                const float sc = sredS[g0] + sredS[g0+4] + sredS[g0+8] + sredS[g0+12];
                const float X  = fmaxf(fmaxf(sredX[g0], sredX[g0+4]),
                                       fmaxf(sredX[g0+8], sredX[g0+12]));
                const float N  = fminf(fminf(sredN[g0], sredN[g0+4]),
                                       fminf(sredN[g0+8], sredN[g0+12]));
                const float M  = (sc >= 0.f) ? X * sc : N * sc;   // exact max_h(v*s)
                scF[j] = sc * L2E;
                MF[j]  = M * L2E;
            }

            // exp2 on registers + denominator partials
            float d0=0.f, d1=0.f, d2=0.f, d3=0.f;
            #pragma unroll
            for (int i = 0; i < 8; ++i) {
                v[i].x = exp2f(fmaf(v[i].x, scF[0], -MF[0])); d0 += v[i].x;
                v[i].y = exp2f(fmaf(v[i].y, scF[1], -MF[1])); d1 += v[i].y;
                v[i].z = exp2f(fmaf(v[i].z, scF[2], -MF[2])); d2 += v[i].z;
                v[i].w = exp2f(fmaf(v[i].w, scF[3], -MF[3])); d3 += v[i].w;
            }
            #pragma unroll
            for (int off = 16; off; off >>= 1) {
                d0 += __shfl_xor_sync(~0u, d0, off);
                d1 += __shfl_xor_sync(~0u, d1, off);
                d2 += __shfl_xor_sync(~0u, d2, off);
                d3 += __shfl_xor_sync(~0u, d3, off);
            }
            if (l == 0) {
                float* pD = sredD + (q * 4 + rh) * 4;
                pD[0]=d0; pD[1]=d1; pD[2]=d2; pD[3]=d3;
            }
            asm volatile("bar.sync %0, 128;" :: "r"(barid) : "memory");

            float inv[4];
            #pragma unroll
            for (int j = 0; j < 4; ++j) {
                const int g0 = q * 16 + j;
                inv[j] = 1.0f / (sredD[g0] + sredD[g0+4] + sredD[g0+8] + sredD[g0+12]);
            }
            #pragma unroll
            for (int i = 0; i < 8; ++i) {
                float a = fmaf(v[i].x, inv[0], acc[i]);
                a = fmaf(v[i].y, inv[1], a);
                a = fmaf(v[i].z, inv[2], a);
                acc[i] = fmaf(v[i].w, inv[3], a);
            }
        }
        if (bcur >= 0) {
            #pragma unroll
            for (int i = 0; i < 8; ++i)
                atomicAdd(out + bcur * HS + rbase + 32 * i, acc[i]);
        }
    }
}

extern "C" void kernel_launch(void* const* d_in, const int* in_sizes, int n_in,
                              void* d_out, int out_size) {
    const float* dh  = (const float*)d_in[0];
    const float* enc = (const float*)d_in[1];
    if (n_in >= 2 && in_sizes[0] > in_sizes[1]) {
        enc = (const float*)d_in[0];
        dh  = (const float*)d_in[1];
    }
    float* out = (float*)d_out;

    typedef CUresult (*EncodeFn)(
        CUtensorMap*, CUtensorMapDataType, cuuint32_t, void*,
        const cuuint64_t*, const cuuint64_t*, const cuuint32_t*, const cuuint32_t*,
        CUtensorMapInterleave, CUtensorMapSwizzle, CUtensorMapL2promotion,
        CUtensorMapFloatOOBfill);
    void* fp = nullptr;
    cudaDriverEntryPointQueryResult qres;
#if CUDART_VERSION >= 12050
    cudaGetDriverEntryPointByVersion("cuTensorMapEncodeTiled", &fp, 12030,
                                     cudaEnableDefault, &qres);
#else
    cudaGetDriverEntryPoint("cuTensorMapEncodeTiled", &fp, cudaEnableDefault, &qres);
#endif
    CUtensorMap tmap;
    {
        EncodeFn fn = (EncodeFn)fp;
        cuuint64_t dims[3]    = {TS, BB, HS};
        cuuint64_t strides[2] = {TS * 4ull, (cuuint64_t)BB * TS * 4ull};
        cuuint32_t box[3]     = {TCH, 1, 256};   // inner = 64 B == SW64 atom width
        cuuint32_t es[3]      = {1, 1, 1};
        fn(&tmap, CU_TENSOR_MAP_DATA_TYPE_FLOAT32, 3, (void*)enc,
           dims, strides, box, es,
           CU_TENSOR_MAP_INTERLEAVE_NONE, CU_TENSOR_MAP_SWIZZLE_64B,
           CU_TENSOR_MAP_L2_PROMOTION_L2_128B, CU_TENSOR_MAP_FLOAT_OOB_FILL_NONE);
    }

    cudaFuncSetAttribute(attn_main,
                         cudaFuncAttributeMaxDynamicSharedMemorySize, SMEM_BYTES);
    zero_out<<<64, 1024>>>(out);
    attn_main<<<GRIDN, NTHR, SMEM_BYTES>>>(tmap, dh, out);
}